// round 14
// baseline (speedup 1.0000x reference)
#include <cuda_runtime.h>
#include <cuda_fp16.h>
#include <cstdint>
#include <math.h>

#define T_TOK 2048
#define HID   1024
#define DFF   2816
#define NEXP  8
#define TOTR  4096

// ---------------- scratch ----------------
__device__ int    g_idx[T_TOK * 2];
__device__ float  g_comb[T_TOK * 2];
__device__ int    g_counts[NEXP];
__device__ int    g_offsets[NEXP];
__device__ int    g_row_token[TOTR];
__device__ float  g_row_weight[TOTR];
__device__ float  g_importance[NEXP];
__device__ __half g_xh[(size_t)T_TOK * HID];
__device__ __half g_acth[(size_t)TOTR * DFF];
__device__ __half g_w1h[(size_t)NEXP * HID * DFF];
__device__ __half g_w3h[(size_t)NEXP * HID * DFF];
__device__ __half g_w2h[(size_t)NEXP * DFF * HID];

// ---------------- helpers ----------------
__device__ __forceinline__ uint32_t s2u(const void* p) {
    uint32_t a;
    asm("{ .reg .u64 t; cvta.to.shared.u64 t, %1; cvt.u32.u64 %0, t; }" : "=r"(a) : "l"(p));
    return a;
}
__device__ __forceinline__ void cp16(uint32_t s, const void* g) {
    asm volatile("cp.async.cg.shared.global [%0], [%1], 16;" :: "r"(s), "l"(g));
}
#define CP_COMMIT() asm volatile("cp.async.commit_group;" ::: "memory")
#define CP_WAIT(n)  asm volatile("cp.async.wait_group %0;" :: "n"(n) : "memory")

__device__ __forceinline__ void ldsm4(uint32_t* r, uint32_t a) {
    asm volatile("ldmatrix.sync.aligned.m8n8.x4.shared.b16 {%0,%1,%2,%3}, [%4];"
                 : "=r"(r[0]), "=r"(r[1]), "=r"(r[2]), "=r"(r[3]) : "r"(a));
}
__device__ __forceinline__ void ldsm4t(uint32_t* r, uint32_t a) {
    asm volatile("ldmatrix.sync.aligned.m8n8.x4.trans.shared.b16 {%0,%1,%2,%3}, [%4];"
                 : "=r"(r[0]), "=r"(r[1]), "=r"(r[2]), "=r"(r[3]) : "r"(a));
}
__device__ __forceinline__ void mma16(float* d, const uint32_t* a, const uint32_t* b) {
    asm volatile(
        "mma.sync.aligned.m16n8k16.row.col.f32.f16.f16.f32 "
        "{%0,%1,%2,%3}, {%4,%5,%6,%7}, {%8,%9}, {%0,%1,%2,%3};"
        : "+f"(d[0]), "+f"(d[1]), "+f"(d[2]), "+f"(d[3])
        : "r"(a[0]), "r"(a[1]), "r"(a[2]), "r"(a[3]), "r"(b[0]), "r"(b[1]));
}

// smem geometry (halves)
#define AH_STRIDE 40
#define BH_STRIDE 136
#define A_HALVES (128 * AH_STRIDE)
#define B_HALVES (32 * BH_STRIDE)
#define G1_STG_B (A_HALVES * 2 + B_HALVES * 2 * 2)
#define NSTAGE 4
#define G1_SMEM (NSTAGE * G1_STG_B)

// gemm2: 128x64 tile, B stride 72 halves (64 + 8 pad)
#define BH2_STRIDE 72
#define B2_HALVES (32 * BH2_STRIDE)                 // 2304
#define G2_STG_B (A_HALVES * 2 + B2_HALVES * 2)    // 14848 B
#define G2_SMEM (NSTAGE * G2_STG_B)                // 59392 B

// ---------------- fp32 -> fp16 converts (streaming, 2x float4 per thread) ----------------
__device__ __forceinline__ void cvt_store_cs(__half2* d, int i, float4 v) {
    __half2 h0 = __floats2half2_rn(v.x, v.y);
    __half2 h1 = __floats2half2_rn(v.z, v.w);
    int2 u;
    u.x = *(int*)&h0;
    u.y = *(int*)&h1;
    __stcs((int2*)(d + 2 * (size_t)i), u);
}

__global__ void cvt_fp16(const float4* __restrict__ src, __half2* __restrict__ dst, int n4) {
    int i0 = blockIdx.x * (blockDim.x * 2) + threadIdx.x;
#pragma unroll
    for (int j = 0; j < 2; j++) {
        int i = i0 + j * blockDim.x;
        if (i < n4) cvt_store_cs(dst, i, __ldcs(src + i));
    }
}

__global__ void cvt_fp16_w(const float4* __restrict__ wA, __half2* __restrict__ dA,
                           const float4* __restrict__ wB, __half2* __restrict__ dB,
                           int n4) {
    const float4* s = blockIdx.z ? wB : wA;
    __half2* d = blockIdx.z ? dB : dA;
    int i0 = blockIdx.x * (blockDim.x * 2) + threadIdx.x;
#pragma unroll
    for (int j = 0; j < 2; j++) {
        int i = i0 + j * blockDim.x;
        if (i < n4) cvt_store_cs(d, i, __ldcs(s + i));
    }
}

// ---------------- zero / gating(+x convert) / routing(+offsets+aux) ----------------
__global__ void zero_scratch_kernel() {
    int t = threadIdx.x;
    if (t < NEXP) { g_counts[t] = 0; g_importance[t] = 0.f; }
}

__global__ void gating_kernel(const float* __restrict__ x,
                              const float* __restrict__ gw) {
    int warp = (blockIdx.x * blockDim.x + threadIdx.x) >> 5;
    int lid  = threadIdx.x & 31;
    if (warp >= T_TOK) return;
    const float4* xr = (const float4*)(x + (size_t)warp * HID);
    __half2* xh2 = (__half2*)(g_xh + (size_t)warp * HID);

    float p[NEXP];
#pragma unroll
    for (int e = 0; e < NEXP; e++) p[e] = 0.f;
#pragma unroll
    for (int q = 0; q < 8; q++) {
        int idx = q * 32 + lid;
        float4 xv = xr[idx];
        xh2[2 * idx]     = __floats2half2_rn(xv.x, xv.y);
        xh2[2 * idx + 1] = __floats2half2_rn(xv.z, xv.w);
#pragma unroll
        for (int e = 0; e < NEXP; e++) {
            float4 gv = ((const float4*)(gw + e * HID))[idx];
            p[e] += xv.x * gv.x + xv.y * gv.y + xv.z * gv.z + xv.w * gv.w;
        }
    }
#pragma unroll
    for (int e = 0; e < NEXP; e++) {
#pragma unroll
        for (int o = 16; o > 0; o >>= 1)
            p[e] += __shfl_xor_sync(0xFFFFFFFFu, p[e], o);
    }

    if (lid == 0) {
        int t = warp;
        int i0 = 0;
#pragma unroll
        for (int e = 1; e < NEXP; e++) if (p[e] > p[i0]) i0 = e;
        int i1 = -1;
#pragma unroll
        for (int e = 0; e < NEXP; e++) {
            if (e == i0) continue;
            if (i1 < 0 || p[e] > p[i1]) i1 = e;
        }
        float m = p[i0];
        float e1 = expf(p[i1] - m);
        float inv = 1.f / (1.f + e1);
        g_idx[t * 2]      = i0;
        g_idx[t * 2 + 1]  = i1;
        g_comb[t * 2]     = inv;
        g_comb[t * 2 + 1] = e1 * inv;
        atomicAdd(&g_counts[i0], 1);
        atomicAdd(&g_counts[i1], 1);

        float se = 0.f, pe[NEXP];
#pragma unroll
        for (int e = 0; e < NEXP; e++) { pe[e] = expf(p[e] - m); se += pe[e]; }
        float isum = 1.f / se;
#pragma unroll
        for (int e = 0; e < NEXP; e++) atomicAdd(&g_importance[e], pe[e] * isum);
    }
}

__global__ void routing_aux_kernel(float* __restrict__ aux_out, int do_aux) {
    int e = blockIdx.x;
    int tid = threadIdx.x;
    int lane = tid & 31, wrp = tid >> 5;
    __shared__ int wsum[8];

    if (e == 0 && tid == 0 && do_aux) {
        float s = 0.f;
        for (int i = 0; i < NEXP; i++) {
            float usage = (float)g_counts[i] / ((float)(T_TOK * 2) + 1e-9f);
            float imp   = g_importance[i] / (float)T_TOK;
            s += usage * imp;
        }
        float aux = s * (float)NEXP * 0.01f;
        if (aux > 1.f) aux = 1.f;
        *aux_out = aux;
    }

    int base = 0;
    for (int i = 0; i < e; i++) base += g_counts[i];
    if (tid == 0) g_offsets[e] = base;

    for (int t0 = 0; t0 < T_TOK; t0 += 256) {
        int t = t0 + tid;
        int sel = 0; float w = 0.f;
        if (g_idx[2 * t] == e)          { sel = 1; w = g_comb[2 * t]; }
        else if (g_idx[2 * t + 1] == e) { sel = 1; w = g_comb[2 * t + 1]; }
        unsigned m = __ballot_sync(0xFFFFFFFFu, sel);
        if (lane == 0) wsum[wrp] = __popc(m);
        __syncthreads();
        int woff = 0, tot = 0;
#pragma unroll
        for (int i = 0; i < 8; i++) {
            int v = wsum[i];
            tot += v;
            if (i < wrp) woff += v;
        }
        if (sel) {
            int pre = __popc(m & ((1u << lane) - 1u));
            int pos = base + woff + pre;
            g_row_token[pos]  = t;
            g_row_weight[pos] = w;
        }
        base += tot;
        __syncthreads();
    }
}

// ---------------- GEMM1 (unchanged from R13) ----------------
#define G1_KC 32

__global__ __launch_bounds__(256) void gemm1_mma(const __half* __restrict__ xh,
                                                 const __half* __restrict__ w1h,
                                                 const __half* __restrict__ w3h) {
    const int e = blockIdx.z;
    const int count = g_counts[e];
    const int m0 = blockIdx.y * 128;
    if (m0 >= count) return;
    const int n0 = blockIdx.x * 128;
    const int off = g_offsets[e];

    extern __shared__ __half dsm[];
    __shared__ int toks[128];

    const int tid = threadIdx.x;
    const int wid = tid >> 5;
    const int lid = tid & 31;
    const int wm = wid >> 2;
    const int wn = wid & 3;
    const int fr = lid >> 2;
    const int fc = lid & 3;
    const int l8 = lid & 7;
    const int s1 = (lid >> 3) & 1;
    const int s2 = (lid >> 4) & 1;

    if (tid < 128) {
        int r = m0 + tid;
        toks[tid] = (r < count) ? g_row_token[off + r] : 0;
    }
    __syncthreads();

    const __half* W1 = w1h + (size_t)e * HID * DFF + n0;
    const __half* W3 = w3h + (size_t)e * HID * DFF + n0;
    const uint32_t sb = s2u(dsm);

    const uint32_t a_lane = (uint32_t)(((l8 + s1 * 8) * AH_STRIDE + s2 * 8) * 2);
    const uint32_t b_lane = (uint32_t)(((s1 * 8 + l8) * BH_STRIDE + s2 * 8) * 2);

    auto fill = [&](int chunk, int stage) {
        uint32_t base = sb + (uint32_t)stage * G1_STG_B;
        int k0 = chunk * 32;
#pragma unroll
        for (int j = 0; j < 2; j++) {
            int i = tid + j * 256;
            int row = i >> 2, q = i & 3;
            cp16(base + (uint32_t)(row * AH_STRIDE + q * 8) * 2,
                 xh + (size_t)toks[row] * HID + k0 + q * 8);
        }
        uint32_t bb = base + A_HALVES * 2;
#pragma unroll
        for (int j = 0; j < 2; j++) {
            int i = tid + j * 256;
            int k = i >> 4, q = i & 15;
            uint32_t o = (uint32_t)(k * BH_STRIDE + q * 8) * 2;
            cp16(bb + o,                W1 + (size_t)(k0 + k) * DFF + q * 8);
            cp16(bb + B_HALVES * 2 + o, W3 + (size_t)(k0 + k) * DFF + q * 8);
        }
        CP_COMMIT();
    };

    float acc1[4][4][4], acc3[4][4][4];
#pragma unroll
    for (int mi = 0; mi < 4; mi++)
#pragma unroll
        for (int ni = 0; ni < 4; ni++)
#pragma unroll
            for (int v = 0; v < 4; v++) { acc1[mi][ni][v] = 0.f; acc3[mi][ni][v] = 0.f; }

    fill(0, 0); fill(1, 1); fill(2, 2);

    for (int c = 0; c < G1_KC; c++) {
        if (c < G1_KC - 2)       CP_WAIT(2);
        else if (c == G1_KC - 2) CP_WAIT(1);
        else                     CP_WAIT(0);
        __syncthreads();
        if (c + 3 < G1_KC) fill(c + 3, (c + 3) & 3);

        uint32_t stA  = sb + (uint32_t)(c & 3) * G1_STG_B;
        uint32_t stB1 = stA + A_HALVES * 2;
        uint32_t stB3 = stB1 + B_HALVES * 2;

#pragma unroll
        for (int ks = 0; ks < 2; ks++) {
            int kk = ks * 16;
            uint32_t afr[4][4];
#pragma unroll
            for (int mi = 0; mi < 4; mi++)
                ldsm4(afr[mi], stA + (uint32_t)((wm * 64 + mi * 16) * AH_STRIDE + kk) * 2 + a_lane);
            uint32_t b1f[2][4], b3f[2][4];
#pragma unroll
            for (int np = 0; np < 2; np++) {
                uint32_t ba = (uint32_t)(kk * BH_STRIDE + wn * 32 + np * 16) * 2 + b_lane;
                ldsm4t(b1f[np], stB1 + ba);
                ldsm4t(b3f[np], stB3 + ba);
            }
#pragma unroll
            for (int mi = 0; mi < 4; mi++)
#pragma unroll
                for (int np = 0; np < 2; np++) {
                    mma16(acc1[mi][np * 2],     afr[mi], &b1f[np][0]);
                    mma16(acc1[mi][np * 2 + 1], afr[mi], &b1f[np][2]);
                    mma16(acc3[mi][np * 2],     afr[mi], &b3f[np][0]);
                    mma16(acc3[mi][np * 2 + 1], afr[mi], &b3f[np][2]);
                }
        }
    }

#pragma unroll
    for (int mi = 0; mi < 4; mi++) {
        int rA = m0 + wm * 64 + mi * 16 + fr;
        int rB = rA + 8;
#pragma unroll
        for (int ni = 0; ni < 4; ni++) {
            int col = n0 + wn * 32 + ni * 8 + fc * 2;
            if (rA < count) {
                float h0 = acc1[mi][ni][0], h1 = acc1[mi][ni][1];
                float ox = (h0 / (1.f + __expf(-h0))) * acc3[mi][ni][0];
                float oy = (h1 / (1.f + __expf(-h1))) * acc3[mi][ni][1];
                *(__half2*)(g_acth + (size_t)(off + rA) * DFF + col) = __floats2half2_rn(ox, oy);
            }
            if (rB < count) {
                float h2 = acc1[mi][ni][2], h3 = acc1[mi][ni][3];
                float ox = (h2 / (1.f + __expf(-h2))) * acc3[mi][ni][2];
                float oy = (h3 / (1.f + __expf(-h3))) * acc3[mi][ni][3];
                *(__half2*)(g_acth + (size_t)(off + rB) * DFF + col) = __floats2half2_rn(ox, oy);
            }
        }
    }
}

// ---------------- GEMM2: 128x64 tile, 2 CTAs/SM ----------------
#define G2_KC 88

__global__ __launch_bounds__(256, 2) void gemm2_mma(const __half* __restrict__ w2h,
                                                    float* __restrict__ out) {
    const int e = blockIdx.z;
    const int count = g_counts[e];
    const int m0 = blockIdx.y * 128;
    if (m0 >= count) return;
    const int n0 = blockIdx.x * 64;
    const int off = g_offsets[e];

    extern __shared__ __half dsm[];
    __shared__ int   toks[128];
    __shared__ float wts[128];

    const int tid = threadIdx.x;
    const int wid = tid >> 5;
    const int lid = tid & 31;
    const int wm = wid >> 1;          // 0..3 (32 rows each)
    const int wn = wid & 1;           // 0..1 (32 cols each)
    const int fr = lid >> 2;
    const int fc = lid & 3;
    const int l8 = lid & 7;
    const int s1 = (lid >> 3) & 1;
    const int s2 = (lid >> 4) & 1;

    if (tid < 128) {
        int r = m0 + tid;
        bool ok = r < count;
        toks[tid] = ok ? g_row_token[off + r] : 0;
        wts[tid]  = ok ? g_row_weight[off + r] : 0.f;
    }
    __syncthreads();

    const __half* W2 = w2h + (size_t)e * DFF * HID + n0;
    const uint32_t sb = s2u(dsm);
    const int arow_base = off + m0;

    const uint32_t a_lane = (uint32_t)(((l8 + s1 * 8) * AH_STRIDE + s2 * 8) * 2);
    const uint32_t b_lane = (uint32_t)(((s1 * 8 + l8) * BH2_STRIDE + s2 * 8) * 2);

    auto fill = [&](int chunk, int stage) {
        uint32_t base = sb + (uint32_t)stage * G2_STG_B;
        int k0 = chunk * 32;
#pragma unroll
        for (int j = 0; j < 2; j++) {
            int i = tid + j * 256;
            int row = i >> 2, q = i & 3;
            int ridx = arow_base + row;
            if (ridx > TOTR - 1) ridx = TOTR - 1;
            cp16(base + (uint32_t)(row * AH_STRIDE + q * 8) * 2,
                 g_acth + (size_t)ridx * DFF + k0 + q * 8);
        }
        // B: 32 k-rows x 64 cols = 256 cp16 (one per thread)
        uint32_t bb = base + A_HALVES * 2;
        int k = tid >> 3, q = tid & 7;
        cp16(bb + (uint32_t)(k * BH2_STRIDE + q * 8) * 2,
             W2 + (size_t)(k0 + k) * HID + q * 8);
        CP_COMMIT();
    };

    float acc[2][4][4];
#pragma unroll
    for (int mi = 0; mi < 2; mi++)
#pragma unroll
        for (int ni = 0; ni < 4; ni++)
#pragma unroll
            for (int v = 0; v < 4; v++) acc[mi][ni][v] = 0.f;

    fill(0, 0); fill(1, 1); fill(2, 2);

    for (int c = 0; c < G2_KC; c++) {
        if (c < G2_KC - 2)       CP_WAIT(2);
        else if (c == G2_KC - 2) CP_WAIT(1);
        else                     CP_WAIT(0);
        __syncthreads();
        if (c + 3 < G2_KC) fill(c + 3, (c + 3) & 3);

        uint32_t stA = sb + (uint32_t)(c & 3) * G2_STG_B;
        uint32_t stB = stA + A_HALVES * 2;

#pragma unroll
        for (int ks = 0; ks < 2; ks++) {
            int kk = ks * 16;
            uint32_t afr[2][4];
#pragma unroll
            for (int mi = 0; mi < 2; mi++)
                ldsm4(afr[mi], stA + (uint32_t)((wm * 32 + mi * 16) * AH_STRIDE + kk) * 2 + a_lane);
            uint32_t bf[2][4];
#pragma unroll
            for (int np = 0; np < 2; np++)
                ldsm4t(bf[np], stB + (uint32_t)(kk * BH2_STRIDE + wn * 32 + np * 16) * 2 + b_lane);
#pragma unroll
            for (int mi = 0; mi < 2; mi++)
#pragma unroll
                for (int np = 0; np < 2; np++) {
                    mma16(acc[mi][np * 2],     afr[mi], &bf[np][0]);
                    mma16(acc[mi][np * 2 + 1], afr[mi], &bf[np][2]);
                }
        }
    }

#pragma unroll
    for (int mi = 0; mi < 2; mi++) {
        int mlA = wm * 32 + mi * 16 + fr;
        int mlB = mlA + 8;
        int rA = m0 + mlA, rB = m0 + mlB;
        int tkA = toks[mlA], tkB = toks[mlB];
        float wA = wts[mlA], wB = wts[mlB];
#pragma unroll
        for (int ni = 0; ni < 4; ni++) {
            int col = n0 + wn * 32 + ni * 8 + fc * 2;
            if (rA < count) {
                float* d = out + (size_t)tkA * HID + col;
                atomicAdd(d,     wA * acc[mi][ni][0]);
                atomicAdd(d + 1, wA * acc[mi][ni][1]);
            }
            if (rB < count) {
                float* d = out + (size_t)tkB * HID + col;
                atomicAdd(d,     wB * acc[mi][ni][2]);
                atomicAdd(d + 1, wB * acc[mi][ni][3]);
            }
        }
    }
}

// ---------------- launch ----------------
extern "C" void kernel_launch(void* const* d_in, const int* in_sizes, int n_in,
                              void* d_out, int out_size) {
    const float* x  = (const float*)d_in[0];
    const float* gw = (const float*)d_in[1];
    const float* w1 = (const float*)d_in[2];
    const float* w3 = (const float*)d_in[3];
    const float* w2 = (const float*)d_in[4];
    float* out = (float*)d_out;

    void *p_xh, *p_w1h, *p_w3h, *p_w2h;
    cudaGetSymbolAddress(&p_xh,  g_xh);
    cudaGetSymbolAddress(&p_w1h, g_w1h);
    cudaGetSymbolAddress(&p_w3h, g_w3h);
    cudaGetSymbolAddress(&p_w2h, g_w2h);

    static cudaStream_t sB = nullptr, sC = nullptr;
    static cudaEvent_t evFork = nullptr, evA = nullptr, evB = nullptr, evC = nullptr;
    static bool inited = false;
    if (!inited) {
        cudaStreamCreateWithFlags(&sB, cudaStreamNonBlocking);
        cudaStreamCreateWithFlags(&sC, cudaStreamNonBlocking);
        cudaEventCreateWithFlags(&evFork, cudaEventDisableTiming);
        cudaEventCreateWithFlags(&evA, cudaEventDisableTiming);
        cudaEventCreateWithFlags(&evB, cudaEventDisableTiming);
        cudaEventCreateWithFlags(&evC, cudaEventDisableTiming);
        cudaFuncSetAttribute(gemm1_mma, cudaFuncAttributeMaxDynamicSharedMemorySize, G1_SMEM + 1024);
        cudaFuncSetAttribute(gemm2_mma, cudaFuncAttributeMaxDynamicSharedMemorySize, G2_SMEM + 1024);
        inited = true;
    }

    const int n4w = NEXP * HID * DFF / 4;

    cudaEventRecord(evFork, 0);
    cudaStreamWaitEvent(sB, evFork, 0);
    cudaStreamWaitEvent(sC, evFork, 0);

    // branch B: routing chain (gating also converts x to fp16)
    zero_scratch_kernel<<<1, 32, 0, sB>>>();
    gating_kernel<<<T_TOK / 8, 256, 0, sB>>>(x, gw);
    routing_aux_kernel<<<NEXP, 256, 0, sB>>>(out + (size_t)T_TOK * HID,
                                             (out_size > T_TOK * HID) ? 1 : 0);
    cudaEventRecord(evB, sB);

    // main: w1+w3 convert (gemm1's prerequisite), streaming + 2x ILP
    {
        dim3 g((n4w + 511) / 512, 1, 2);
        cvt_fp16_w<<<g, 256>>>((const float4*)w1, (__half2*)p_w1h,
                               (const float4*)w3, (__half2*)p_w3h, n4w);
    }
    cudaEventRecord(evA, 0);

    // sC: out zero + w2 convert AFTER cvt13 (hides under gemm1's compute)
    cudaStreamWaitEvent(sC, evA, 0);
    cudaMemsetAsync(out, 0, (size_t)T_TOK * HID * sizeof(float), sC);
    cvt_fp16<<<(n4w + 511) / 512, 256, 0, sC>>>((const float4*)w2, (__half2*)p_w2h, n4w);
    cudaEventRecord(evC, sC);

    // main: gemm1 after routing chain (evB) and cvt13 (program order)
    cudaStreamWaitEvent(0, evB, 0);
    dim3 g1(DFF / 128, T_TOK / 128, NEXP);
    gemm1_mma<<<g1, 256, G1_SMEM + 1024>>>((const __half*)p_xh,
                                           (const __half*)p_w1h,
                                           (const __half*)p_w3h);

    // main: gemm2 (128x64 tiles, 2 CTAs/SM) after w2 convert + out zero
    cudaStreamWaitEvent(0, evC, 0);
    dim3 g2(HID / 64, T_TOK / 128, NEXP);
    gemm2_mma<<<g2, 256, G2_SMEM + 1024>>>((const __half*)p_w2h, out);
}

// round 15
// speedup vs baseline: 1.0772x; 1.0772x over previous
#include <cuda_runtime.h>
#include <cuda_fp16.h>
#include <cstdint>
#include <math.h>

#define T_TOK 2048
#define HID   1024
#define DFF   2816
#define NEXP  8
#define TOTR  4096

// ---------------- scratch ----------------
__device__ int    g_idx[T_TOK * 2];
__device__ float  g_comb[T_TOK * 2];
__device__ int    g_counts[NEXP];
__device__ int    g_offsets[NEXP];
__device__ int    g_row_token[TOTR];
__device__ float  g_row_weight[TOTR];
__device__ float  g_importance[NEXP];
__device__ __half g_xh[(size_t)T_TOK * HID];
__device__ __half g_acth[(size_t)TOTR * DFF];
__device__ __half g_w1h[(size_t)NEXP * HID * DFF];
__device__ __half g_w3h[(size_t)NEXP * HID * DFF];
__device__ __half g_w2h[(size_t)NEXP * DFF * HID];

// ---------------- helpers ----------------
__device__ __forceinline__ uint32_t s2u(const void* p) {
    uint32_t a;
    asm("{ .reg .u64 t; cvta.to.shared.u64 t, %1; cvt.u32.u64 %0, t; }" : "=r"(a) : "l"(p));
    return a;
}
__device__ __forceinline__ void cp16(uint32_t s, const void* g) {
    asm volatile("cp.async.cg.shared.global [%0], [%1], 16;" :: "r"(s), "l"(g));
}
#define CP_COMMIT() asm volatile("cp.async.commit_group;" ::: "memory")
#define CP_WAIT(n)  asm volatile("cp.async.wait_group %0;" :: "n"(n) : "memory")

__device__ __forceinline__ void ldsm4(uint32_t* r, uint32_t a) {
    asm volatile("ldmatrix.sync.aligned.m8n8.x4.shared.b16 {%0,%1,%2,%3}, [%4];"
                 : "=r"(r[0]), "=r"(r[1]), "=r"(r[2]), "=r"(r[3]) : "r"(a));
}
__device__ __forceinline__ void ldsm4t(uint32_t* r, uint32_t a) {
    asm volatile("ldmatrix.sync.aligned.m8n8.x4.trans.shared.b16 {%0,%1,%2,%3}, [%4];"
                 : "=r"(r[0]), "=r"(r[1]), "=r"(r[2]), "=r"(r[3]) : "r"(a));
}
__device__ __forceinline__ void mma16(float* d, const uint32_t* a, const uint32_t* b) {
    asm volatile(
        "mma.sync.aligned.m16n8k16.row.col.f32.f16.f16.f32 "
        "{%0,%1,%2,%3}, {%4,%5,%6,%7}, {%8,%9}, {%0,%1,%2,%3};"
        : "+f"(d[0]), "+f"(d[1]), "+f"(d[2]), "+f"(d[3])
        : "r"(a[0]), "r"(a[1]), "r"(a[2]), "r"(a[3]), "r"(b[0]), "r"(b[1]));
}

// smem geometry (halves)
#define AH_STRIDE 40
#define BH_STRIDE 136
#define A_HALVES (128 * AH_STRIDE)
#define B_HALVES (32 * BH_STRIDE)
#define G1_STG_B (A_HALVES * 2 + B_HALVES * 2 * 2)
#define G2_STG_B (A_HALVES * 2 + B_HALVES * 2)
#define NSTAGE 4
#define G1_SMEM (NSTAGE * G1_STG_B)
#define G2_SMEM (NSTAGE * G2_STG_B)

// ---------------- fp32 -> fp16 converts (streaming, 2x float4 per thread) ----------------
__device__ __forceinline__ void cvt_store_cs(__half2* d, int i, float4 v) {
    __half2 h0 = __floats2half2_rn(v.x, v.y);
    __half2 h1 = __floats2half2_rn(v.z, v.w);
    int2 u;
    u.x = *(int*)&h0;
    u.y = *(int*)&h1;
    __stcs((int2*)(d + 2 * (size_t)i), u);
}

__global__ void cvt_fp16(const float4* __restrict__ src, __half2* __restrict__ dst, int n4) {
    int i0 = blockIdx.x * (blockDim.x * 2) + threadIdx.x;
#pragma unroll
    for (int j = 0; j < 2; j++) {
        int i = i0 + j * blockDim.x;
        if (i < n4) cvt_store_cs(dst, i, __ldcs(src + i));
    }
}

__global__ void cvt_fp16_w(const float4* __restrict__ wA, __half2* __restrict__ dA,
                           const float4* __restrict__ wB, __half2* __restrict__ dB,
                           int n4) {
    const float4* s = blockIdx.z ? wB : wA;
    __half2* d = blockIdx.z ? dB : dA;
    int i0 = blockIdx.x * (blockDim.x * 2) + threadIdx.x;
#pragma unroll
    for (int j = 0; j < 2; j++) {
        int i = i0 + j * blockDim.x;
        if (i < n4) cvt_store_cs(d, i, __ldcs(s + i));
    }
}

// ---------------- zero / gating(+x convert) / routing(+offsets+aux) ----------------
__global__ void zero_scratch_kernel() {
    int t = threadIdx.x;
    if (t < NEXP) { g_counts[t] = 0; g_importance[t] = 0.f; }
}

// warp per token: gating logits + top-2 + importance, AND fp16 conversion of x
__global__ void gating_kernel(const float* __restrict__ x,
                              const float* __restrict__ gw) {
    int warp = (blockIdx.x * blockDim.x + threadIdx.x) >> 5;
    int lid  = threadIdx.x & 31;
    if (warp >= T_TOK) return;
    const float4* xr = (const float4*)(x + (size_t)warp * HID);
    __half2* xh2 = (__half2*)(g_xh + (size_t)warp * HID);

    float p[NEXP];
#pragma unroll
    for (int e = 0; e < NEXP; e++) p[e] = 0.f;
#pragma unroll
    for (int q = 0; q < 8; q++) {
        int idx = q * 32 + lid;
        float4 xv = xr[idx];
        // fused x fp32 -> fp16 store (NOT streaming: reused 22x by gemm1)
        xh2[2 * idx]     = __floats2half2_rn(xv.x, xv.y);
        xh2[2 * idx + 1] = __floats2half2_rn(xv.z, xv.w);
#pragma unroll
        for (int e = 0; e < NEXP; e++) {
            float4 gv = ((const float4*)(gw + e * HID))[idx];
            p[e] += xv.x * gv.x + xv.y * gv.y + xv.z * gv.z + xv.w * gv.w;
        }
    }
#pragma unroll
    for (int e = 0; e < NEXP; e++) {
#pragma unroll
        for (int o = 16; o > 0; o >>= 1)
            p[e] += __shfl_xor_sync(0xFFFFFFFFu, p[e], o);
    }

    if (lid == 0) {
        int t = warp;
        int i0 = 0;
#pragma unroll
        for (int e = 1; e < NEXP; e++) if (p[e] > p[i0]) i0 = e;
        int i1 = -1;
#pragma unroll
        for (int e = 0; e < NEXP; e++) {
            if (e == i0) continue;
            if (i1 < 0 || p[e] > p[i1]) i1 = e;
        }
        float m = p[i0];
        float e1 = expf(p[i1] - m);
        float inv = 1.f / (1.f + e1);
        g_idx[t * 2]      = i0;
        g_idx[t * 2 + 1]  = i1;
        g_comb[t * 2]     = inv;
        g_comb[t * 2 + 1] = e1 * inv;
        atomicAdd(&g_counts[i0], 1);
        atomicAdd(&g_counts[i1], 1);

        float se = 0.f, pe[NEXP];
#pragma unroll
        for (int e = 0; e < NEXP; e++) { pe[e] = expf(p[e] - m); se += pe[e]; }
        float isum = 1.f / se;
#pragma unroll
        for (int e = 0; e < NEXP; e++) atomicAdd(&g_importance[e], pe[e] * isum);
    }
}

// routing with fused offsets + aux, ballot-scan
__global__ void routing_aux_kernel(float* __restrict__ aux_out, int do_aux) {
    int e = blockIdx.x;
    int tid = threadIdx.x;
    int lane = tid & 31, wrp = tid >> 5;
    __shared__ int wsum[8];

    if (e == 0 && tid == 0 && do_aux) {
        float s = 0.f;
        for (int i = 0; i < NEXP; i++) {
            float usage = (float)g_counts[i] / ((float)(T_TOK * 2) + 1e-9f);
            float imp   = g_importance[i] / (float)T_TOK;
            s += usage * imp;
        }
        float aux = s * (float)NEXP * 0.01f;
        if (aux > 1.f) aux = 1.f;
        *aux_out = aux;
    }

    int base = 0;
    for (int i = 0; i < e; i++) base += g_counts[i];
    if (tid == 0) g_offsets[e] = base;

    for (int t0 = 0; t0 < T_TOK; t0 += 256) {
        int t = t0 + tid;
        int sel = 0; float w = 0.f;
        if (g_idx[2 * t] == e)          { sel = 1; w = g_comb[2 * t]; }
        else if (g_idx[2 * t + 1] == e) { sel = 1; w = g_comb[2 * t + 1]; }
        unsigned m = __ballot_sync(0xFFFFFFFFu, sel);
        if (lane == 0) wsum[wrp] = __popc(m);
        __syncthreads();
        int woff = 0, tot = 0;
#pragma unroll
        for (int i = 0; i < 8; i++) {
            int v = wsum[i];
            tot += v;
            if (i < wrp) woff += v;
        }
        if (sel) {
            int pre = __popc(m & ((1u << lane) - 1u));
            int pos = base + woff + pre;
            g_row_token[pos]  = t;
            g_row_weight[pos] = w;
        }
        base += tot;
        __syncthreads();
    }
}

// ---------------- GEMM1 ----------------
#define G1_KC 32

__global__ __launch_bounds__(256) void gemm1_mma(const __half* __restrict__ xh,
                                                 const __half* __restrict__ w1h,
                                                 const __half* __restrict__ w3h) {
    const int e = blockIdx.z;
    const int count = g_counts[e];
    const int m0 = blockIdx.y * 128;
    if (m0 >= count) return;
    const int n0 = blockIdx.x * 128;
    const int off = g_offsets[e];

    extern __shared__ __half dsm[];
    __shared__ int toks[128];

    const int tid = threadIdx.x;
    const int wid = tid >> 5;
    const int lid = tid & 31;
    const int wm = wid >> 2;
    const int wn = wid & 3;
    const int fr = lid >> 2;
    const int fc = lid & 3;
    const int l8 = lid & 7;
    const int s1 = (lid >> 3) & 1;
    const int s2 = (lid >> 4) & 1;

    if (tid < 128) {
        int r = m0 + tid;
        toks[tid] = (r < count) ? g_row_token[off + r] : 0;
    }
    __syncthreads();

    const __half* W1 = w1h + (size_t)e * HID * DFF + n0;
    const __half* W3 = w3h + (size_t)e * HID * DFF + n0;
    const uint32_t sb = s2u(dsm);

    const uint32_t a_lane = (uint32_t)(((l8 + s1 * 8) * AH_STRIDE + s2 * 8) * 2);
    const uint32_t b_lane = (uint32_t)(((s1 * 8 + l8) * BH_STRIDE + s2 * 8) * 2);

    auto fill = [&](int chunk, int stage) {
        uint32_t base = sb + (uint32_t)stage * G1_STG_B;
        int k0 = chunk * 32;
#pragma unroll
        for (int j = 0; j < 2; j++) {
            int i = tid + j * 256;
            int row = i >> 2, q = i & 3;
            cp16(base + (uint32_t)(row * AH_STRIDE + q * 8) * 2,
                 xh + (size_t)toks[row] * HID + k0 + q * 8);
        }
        uint32_t bb = base + A_HALVES * 2;
#pragma unroll
        for (int j = 0; j < 2; j++) {
            int i = tid + j * 256;
            int k = i >> 4, q = i & 15;
            uint32_t o = (uint32_t)(k * BH_STRIDE + q * 8) * 2;
            cp16(bb + o,                W1 + (size_t)(k0 + k) * DFF + q * 8);
            cp16(bb + B_HALVES * 2 + o, W3 + (size_t)(k0 + k) * DFF + q * 8);
        }
        CP_COMMIT();
    };

    float acc1[4][4][4], acc3[4][4][4];
#pragma unroll
    for (int mi = 0; mi < 4; mi++)
#pragma unroll
        for (int ni = 0; ni < 4; ni++)
#pragma unroll
            for (int v = 0; v < 4; v++) { acc1[mi][ni][v] = 0.f; acc3[mi][ni][v] = 0.f; }

    fill(0, 0); fill(1, 1); fill(2, 2);

    for (int c = 0; c < G1_KC; c++) {
        if (c < G1_KC - 2)       CP_WAIT(2);
        else if (c == G1_KC - 2) CP_WAIT(1);
        else                     CP_WAIT(0);
        __syncthreads();
        if (c + 3 < G1_KC) fill(c + 3, (c + 3) & 3);

        uint32_t stA  = sb + (uint32_t)(c & 3) * G1_STG_B;
        uint32_t stB1 = stA + A_HALVES * 2;
        uint32_t stB3 = stB1 + B_HALVES * 2;

#pragma unroll
        for (int ks = 0; ks < 2; ks++) {
            int kk = ks * 16;
            uint32_t afr[4][4];
#pragma unroll
            for (int mi = 0; mi < 4; mi++)
                ldsm4(afr[mi], stA + (uint32_t)((wm * 64 + mi * 16) * AH_STRIDE + kk) * 2 + a_lane);
            uint32_t b1f[2][4], b3f[2][4];
#pragma unroll
            for (int np = 0; np < 2; np++) {
                uint32_t ba = (uint32_t)(kk * BH_STRIDE + wn * 32 + np * 16) * 2 + b_lane;
                ldsm4t(b1f[np], stB1 + ba);
                ldsm4t(b3f[np], stB3 + ba);
            }
#pragma unroll
            for (int mi = 0; mi < 4; mi++)
#pragma unroll
                for (int np = 0; np < 2; np++) {
                    mma16(acc1[mi][np * 2],     afr[mi], &b1f[np][0]);
                    mma16(acc1[mi][np * 2 + 1], afr[mi], &b1f[np][2]);
                    mma16(acc3[mi][np * 2],     afr[mi], &b3f[np][0]);
                    mma16(acc3[mi][np * 2 + 1], afr[mi], &b3f[np][2]);
                }
        }
    }

#pragma unroll
    for (int mi = 0; mi < 4; mi++) {
        int rA = m0 + wm * 64 + mi * 16 + fr;
        int rB = rA + 8;
#pragma unroll
        for (int ni = 0; ni < 4; ni++) {
            int col = n0 + wn * 32 + ni * 8 + fc * 2;
            if (rA < count) {
                float h0 = acc1[mi][ni][0], h1 = acc1[mi][ni][1];
                float ox = (h0 / (1.f + __expf(-h0))) * acc3[mi][ni][0];
                float oy = (h1 / (1.f + __expf(-h1))) * acc3[mi][ni][1];
                *(__half2*)(g_acth + (size_t)(off + rA) * DFF + col) = __floats2half2_rn(ox, oy);
            }
            if (rB < count) {
                float h2 = acc1[mi][ni][2], h3 = acc1[mi][ni][3];
                float ox = (h2 / (1.f + __expf(-h2))) * acc3[mi][ni][2];
                float oy = (h3 / (1.f + __expf(-h3))) * acc3[mi][ni][3];
                *(__half2*)(g_acth + (size_t)(off + rB) * DFF + col) = __floats2half2_rn(ox, oy);
            }
        }
    }
}

// ---------------- GEMM2 ----------------
#define G2_KC 88

__global__ __launch_bounds__(256) void gemm2_mma(const __half* __restrict__ w2h,
                                                 float* __restrict__ out) {
    const int e = blockIdx.z;
    const int count = g_counts[e];
    const int m0 = blockIdx.y * 128;
    if (m0 >= count) return;
    const int n0 = blockIdx.x * 128;
    const int off = g_offsets[e];

    extern __shared__ __half dsm[];
    __shared__ int   toks[128];
    __shared__ float wts[128];

    const int tid = threadIdx.x;
    const int wid = tid >> 5;
    const int lid = tid & 31;
    const int wm = wid >> 2;
    const int wn = wid & 3;
    const int fr = lid >> 2;
    const int fc = lid & 3;
    const int l8 = lid & 7;
    const int s1 = (lid >> 3) & 1;
    const int s2 = (lid >> 4) & 1;

    if (tid < 128) {
        int r = m0 + tid;
        bool ok = r < count;
        toks[tid] = ok ? g_row_token[off + r] : 0;
        wts[tid]  = ok ? g_row_weight[off + r] : 0.f;
    }
    __syncthreads();

    const __half* W2 = w2h + (size_t)e * DFF * HID + n0;
    const uint32_t sb = s2u(dsm);
    const int arow_base = off + m0;

    const uint32_t a_lane = (uint32_t)(((l8 + s1 * 8) * AH_STRIDE + s2 * 8) * 2);
    const uint32_t b_lane = (uint32_t)(((s1 * 8 + l8) * BH_STRIDE + s2 * 8) * 2);

    auto fill = [&](int chunk, int stage) {
        uint32_t base = sb + (uint32_t)stage * G2_STG_B;
        int k0 = chunk * 32;
#pragma unroll
        for (int j = 0; j < 2; j++) {
            int i = tid + j * 256;
            int row = i >> 2, q = i & 3;
            int ridx = arow_base + row;
            if (ridx > TOTR - 1) ridx = TOTR - 1;
            cp16(base + (uint32_t)(row * AH_STRIDE + q * 8) * 2,
                 g_acth + (size_t)ridx * DFF + k0 + q * 8);
        }
        uint32_t bb = base + A_HALVES * 2;
#pragma unroll
        for (int j = 0; j < 2; j++) {
            int i = tid + j * 256;
            int k = i >> 4, q = i & 15;
            cp16(bb + (uint32_t)(k * BH_STRIDE + q * 8) * 2,
                 W2 + (size_t)(k0 + k) * HID + q * 8);
        }
        CP_COMMIT();
    };

    float acc[4][4][4];
#pragma unroll
    for (int mi = 0; mi < 4; mi++)
#pragma unroll
        for (int ni = 0; ni < 4; ni++)
#pragma unroll
            for (int v = 0; v < 4; v++) acc[mi][ni][v] = 0.f;

    fill(0, 0); fill(1, 1); fill(2, 2);

    for (int c = 0; c < G2_KC; c++) {
        if (c < G2_KC - 2)       CP_WAIT(2);
        else if (c == G2_KC - 2) CP_WAIT(1);
        else                     CP_WAIT(0);
        __syncthreads();
        if (c + 3 < G2_KC) fill(c + 3, (c + 3) & 3);

        uint32_t stA = sb + (uint32_t)(c & 3) * G2_STG_B;
        uint32_t stB = stA + A_HALVES * 2;

#pragma unroll
        for (int ks = 0; ks < 2; ks++) {
            int kk = ks * 16;
            uint32_t afr[4][4];
#pragma unroll
            for (int mi = 0; mi < 4; mi++)
                ldsm4(afr[mi], stA + (uint32_t)((wm * 64 + mi * 16) * AH_STRIDE + kk) * 2 + a_lane);
            uint32_t bf[2][4];
#pragma unroll
            for (int np = 0; np < 2; np++)
                ldsm4t(bf[np], stB + (uint32_t)(kk * BH_STRIDE + wn * 32 + np * 16) * 2 + b_lane);
#pragma unroll
            for (int mi = 0; mi < 4; mi++)
#pragma unroll
                for (int np = 0; np < 2; np++) {
                    mma16(acc[mi][np * 2],     afr[mi], &bf[np][0]);
                    mma16(acc[mi][np * 2 + 1], afr[mi], &bf[np][2]);
                }
        }
    }

#pragma unroll
    for (int mi = 0; mi < 4; mi++) {
        int mlA = wm * 64 + mi * 16 + fr;
        int mlB = mlA + 8;
        int rA = m0 + mlA, rB = m0 + mlB;
        int tkA = toks[mlA], tkB = toks[mlB];
        float wA = wts[mlA], wB = wts[mlB];
#pragma unroll
        for (int ni = 0; ni < 4; ni++) {
            int col = n0 + wn * 32 + ni * 8 + fc * 2;
            if (rA < count) {
                float* d = out + (size_t)tkA * HID + col;
                atomicAdd(d,     wA * acc[mi][ni][0]);
                atomicAdd(d + 1, wA * acc[mi][ni][1]);
            }
            if (rB < count) {
                float* d = out + (size_t)tkB * HID + col;
                atomicAdd(d,     wB * acc[mi][ni][2]);
                atomicAdd(d + 1, wB * acc[mi][ni][3]);
            }
        }
    }
}

// ---------------- launch ----------------
extern "C" void kernel_launch(void* const* d_in, const int* in_sizes, int n_in,
                              void* d_out, int out_size) {
    const float* x  = (const float*)d_in[0];
    const float* gw = (const float*)d_in[1];
    const float* w1 = (const float*)d_in[2];
    const float* w3 = (const float*)d_in[3];
    const float* w2 = (const float*)d_in[4];
    float* out = (float*)d_out;

    void *p_xh, *p_w1h, *p_w3h, *p_w2h;
    cudaGetSymbolAddress(&p_xh,  g_xh);
    cudaGetSymbolAddress(&p_w1h, g_w1h);
    cudaGetSymbolAddress(&p_w3h, g_w3h);
    cudaGetSymbolAddress(&p_w2h, g_w2h);

    static cudaStream_t sB = nullptr, sC = nullptr;
    static cudaEvent_t evFork = nullptr, evA = nullptr, evB = nullptr, evC = nullptr;
    static bool inited = false;
    if (!inited) {
        cudaStreamCreateWithFlags(&sB, cudaStreamNonBlocking);
        cudaStreamCreateWithFlags(&sC, cudaStreamNonBlocking);
        cudaEventCreateWithFlags(&evFork, cudaEventDisableTiming);
        cudaEventCreateWithFlags(&evA, cudaEventDisableTiming);
        cudaEventCreateWithFlags(&evB, cudaEventDisableTiming);
        cudaEventCreateWithFlags(&evC, cudaEventDisableTiming);
        cudaFuncSetAttribute(gemm1_mma, cudaFuncAttributeMaxDynamicSharedMemorySize, G1_SMEM + 1024);
        cudaFuncSetAttribute(gemm2_mma, cudaFuncAttributeMaxDynamicSharedMemorySize, G2_SMEM + 1024);
        inited = true;
    }

    const int n4w = NEXP * HID * DFF / 4;

    cudaEventRecord(evFork, 0);
    cudaStreamWaitEvent(sB, evFork, 0);
    cudaStreamWaitEvent(sC, evFork, 0);

    // branch B: routing chain (gating also converts x to fp16)
    zero_scratch_kernel<<<1, 32, 0, sB>>>();
    gating_kernel<<<T_TOK / 8, 256, 0, sB>>>(x, gw);
    routing_aux_kernel<<<NEXP, 256, 0, sB>>>(out + (size_t)T_TOK * HID,
                                             (out_size > T_TOK * HID) ? 1 : 0);
    cudaEventRecord(evB, sB);

    // main: w1+w3 convert (gemm1's prerequisite), 2x float4/thread + streaming
    {
        dim3 g((n4w + 511) / 512, 1, 2);
        cvt_fp16_w<<<g, 256>>>((const float4*)w1, (__half2*)p_w1h,
                               (const float4*)w3, (__half2*)p_w3h, n4w);
    }
    cudaEventRecord(evA, 0);

    // sC: out zero + w2 convert AFTER cvt13 (hides under gemm1's compute)
    cudaStreamWaitEvent(sC, evA, 0);
    cudaMemsetAsync(out, 0, (size_t)T_TOK * HID * sizeof(float), sC);
    cvt_fp16<<<(n4w + 511) / 512, 256, 0, sC>>>((const float4*)w2, (__half2*)p_w2h, n4w);
    cudaEventRecord(evC, sC);

    // main: gemm1 after routing chain (evB) and cvt13 (program order)
    cudaStreamWaitEvent(0, evB, 0);
    dim3 g1(DFF / 128, T_TOK / 128, NEXP);
    gemm1_mma<<<g1, 256, G1_SMEM + 1024>>>((const __half*)p_xh,
                                           (const __half*)p_w1h,
                                           (const __half*)p_w3h);

    // main: gemm2 after w2 convert + out zero
    cudaStreamWaitEvent(0, evC, 0);
    dim3 g2(HID / 128, T_TOK / 128, NEXP);
    gemm2_mma<<<g2, 256, G2_SMEM + 1024>>>((const __half*)p_w2h, out);
}

// round 16
// speedup vs baseline: 1.0781x; 1.0008x over previous
#include <cuda_runtime.h>
#include <cuda_fp16.h>
#include <cstdint>
#include <math.h>

#define T_TOK 2048
#define HID   1024
#define DFF   2816
#define NEXP  8
#define TOTR  4096

// ---------------- scratch ----------------
__device__ int    g_idx[T_TOK * 2];
__device__ float  g_comb[T_TOK * 2];
__device__ int    g_counts[NEXP];
__device__ int    g_offsets[NEXP];
__device__ int    g_row_token[TOTR];
__device__ float  g_row_weight[TOTR];
__device__ float  g_importance[NEXP];
__device__ __half g_xh[(size_t)T_TOK * HID];
__device__ __half g_acth[(size_t)TOTR * DFF];
__device__ __half g_w1h[(size_t)NEXP * HID * DFF];
__device__ __half g_w3h[(size_t)NEXP * HID * DFF];
__device__ __half g_w2h[(size_t)NEXP * DFF * HID];

// ---------------- helpers ----------------
__device__ __forceinline__ uint32_t s2u(const void* p) {
    uint32_t a;
    asm("{ .reg .u64 t; cvta.to.shared.u64 t, %1; cvt.u32.u64 %0, t; }" : "=r"(a) : "l"(p));
    return a;
}
__device__ __forceinline__ void cp16(uint32_t s, const void* g) {
    asm volatile("cp.async.cg.shared.global [%0], [%1], 16;" :: "r"(s), "l"(g));
}
#define CP_COMMIT() asm volatile("cp.async.commit_group;" ::: "memory")
#define CP_WAIT(n)  asm volatile("cp.async.wait_group %0;" :: "n"(n) : "memory")

__device__ __forceinline__ void ldsm4(uint32_t* r, uint32_t a) {
    asm volatile("ldmatrix.sync.aligned.m8n8.x4.shared.b16 {%0,%1,%2,%3}, [%4];"
                 : "=r"(r[0]), "=r"(r[1]), "=r"(r[2]), "=r"(r[3]) : "r"(a));
}
__device__ __forceinline__ void ldsm4t(uint32_t* r, uint32_t a) {
    asm volatile("ldmatrix.sync.aligned.m8n8.x4.trans.shared.b16 {%0,%1,%2,%3}, [%4];"
                 : "=r"(r[0]), "=r"(r[1]), "=r"(r[2]), "=r"(r[3]) : "r"(a));
}
__device__ __forceinline__ void mma16(float* d, const uint32_t* a, const uint32_t* b) {
    asm volatile(
        "mma.sync.aligned.m16n8k16.row.col.f32.f16.f16.f32 "
        "{%0,%1,%2,%3}, {%4,%5,%6,%7}, {%8,%9}, {%0,%1,%2,%3};"
        : "+f"(d[0]), "+f"(d[1]), "+f"(d[2]), "+f"(d[3])
        : "r"(a[0]), "r"(a[1]), "r"(a[2]), "r"(a[3]), "r"(b[0]), "r"(b[1]));
}

// smem geometry (halves)
#define AH_STRIDE 40
#define BH_STRIDE 136
#define A_HALVES (128 * AH_STRIDE)
#define B_HALVES (32 * BH_STRIDE)
#define G1_STG_B (A_HALVES * 2 + B_HALVES * 2 * 2)
#define G2_STG_B (A_HALVES * 2 + B_HALVES * 2)
#define NSTAGE 4
#define G1_SMEM (NSTAGE * G1_STG_B)
#define G2_SMEM (NSTAGE * G2_STG_B)

// ---------------- fp32 -> fp16 converts (streaming, 2x float4 per thread) ----------------
__device__ __forceinline__ void cvt_store_cs(__half2* d, int i, float4 v) {
    __half2 h0 = __floats2half2_rn(v.x, v.y);
    __half2 h1 = __floats2half2_rn(v.z, v.w);
    int2 u;
    u.x = *(int*)&h0;
    u.y = *(int*)&h1;
    __stcs((int2*)(d + 2 * (size_t)i), u);
}

__global__ void cvt_fp16(const float4* __restrict__ src, __half2* __restrict__ dst, int n4) {
    int i0 = blockIdx.x * (blockDim.x * 2) + threadIdx.x;
#pragma unroll
    for (int j = 0; j < 2; j++) {
        int i = i0 + j * blockDim.x;
        if (i < n4) cvt_store_cs(dst, i, __ldcs(src + i));
    }
}

__global__ void cvt_fp16_w(const float4* __restrict__ wA, __half2* __restrict__ dA,
                           const float4* __restrict__ wB, __half2* __restrict__ dB,
                           int n4) {
    const float4* s = blockIdx.z ? wB : wA;
    __half2* d = blockIdx.z ? dB : dA;
    int i0 = blockIdx.x * (blockDim.x * 2) + threadIdx.x;
#pragma unroll
    for (int j = 0; j < 2; j++) {
        int i = i0 + j * blockDim.x;
        if (i < n4) cvt_store_cs(d, i, __ldcs(s + i));
    }
}

// ---------------- zero / gating(+x convert) / routing(+offsets+aux) ----------------
__global__ void zero_scratch_kernel() {
    int t = threadIdx.x;
    if (t < NEXP) { g_counts[t] = 0; g_importance[t] = 0.f; }
}

// warp per token: gating logits + top-2 + importance, AND fp16 conversion of x
__global__ void gating_kernel(const float* __restrict__ x,
                              const float* __restrict__ gw) {
    int warp = (blockIdx.x * blockDim.x + threadIdx.x) >> 5;
    int lid  = threadIdx.x & 31;
    if (warp >= T_TOK) return;
    const float4* xr = (const float4*)(x + (size_t)warp * HID);
    __half2* xh2 = (__half2*)(g_xh + (size_t)warp * HID);

    float p[NEXP];
#pragma unroll
    for (int e = 0; e < NEXP; e++) p[e] = 0.f;
#pragma unroll
    for (int q = 0; q < 8; q++) {
        int idx = q * 32 + lid;
        float4 xv = xr[idx];
        // fused x fp32 -> fp16 store (NOT streaming: reused 22x by gemm1)
        xh2[2 * idx]     = __floats2half2_rn(xv.x, xv.y);
        xh2[2 * idx + 1] = __floats2half2_rn(xv.z, xv.w);
#pragma unroll
        for (int e = 0; e < NEXP; e++) {
            float4 gv = ((const float4*)(gw + e * HID))[idx];
            p[e] += xv.x * gv.x + xv.y * gv.y + xv.z * gv.z + xv.w * gv.w;
        }
    }
#pragma unroll
    for (int e = 0; e < NEXP; e++) {
#pragma unroll
        for (int o = 16; o > 0; o >>= 1)
            p[e] += __shfl_xor_sync(0xFFFFFFFFu, p[e], o);
    }

    if (lid == 0) {
        int t = warp;
        int i0 = 0;
#pragma unroll
        for (int e = 1; e < NEXP; e++) if (p[e] > p[i0]) i0 = e;
        int i1 = -1;
#pragma unroll
        for (int e = 0; e < NEXP; e++) {
            if (e == i0) continue;
            if (i1 < 0 || p[e] > p[i1]) i1 = e;
        }
        float m = p[i0];
        float e1 = expf(p[i1] - m);
        float inv = 1.f / (1.f + e1);
        g_idx[t * 2]      = i0;
        g_idx[t * 2 + 1]  = i1;
        g_comb[t * 2]     = inv;
        g_comb[t * 2 + 1] = e1 * inv;
        atomicAdd(&g_counts[i0], 1);
        atomicAdd(&g_counts[i1], 1);

        float se = 0.f, pe[NEXP];
#pragma unroll
        for (int e = 0; e < NEXP; e++) { pe[e] = expf(p[e] - m); se += pe[e]; }
        float isum = 1.f / se;
#pragma unroll
        for (int e = 0; e < NEXP; e++) atomicAdd(&g_importance[e], pe[e] * isum);
    }
}

// routing with fused offsets + aux, ballot-scan
__global__ void routing_aux_kernel(float* __restrict__ aux_out, int do_aux) {
    int e = blockIdx.x;
    int tid = threadIdx.x;
    int lane = tid & 31, wrp = tid >> 5;
    __shared__ int wsum[8];

    if (e == 0 && tid == 0 && do_aux) {
        float s = 0.f;
        for (int i = 0; i < NEXP; i++) {
            float usage = (float)g_counts[i] / ((float)(T_TOK * 2) + 1e-9f);
            float imp   = g_importance[i] / (float)T_TOK;
            s += usage * imp;
        }
        float aux = s * (float)NEXP * 0.01f;
        if (aux > 1.f) aux = 1.f;
        *aux_out = aux;
    }

    int base = 0;
    for (int i = 0; i < e; i++) base += g_counts[i];
    if (tid == 0) g_offsets[e] = base;

    for (int t0 = 0; t0 < T_TOK; t0 += 256) {
        int t = t0 + tid;
        int sel = 0; float w = 0.f;
        if (g_idx[2 * t] == e)          { sel = 1; w = g_comb[2 * t]; }
        else if (g_idx[2 * t + 1] == e) { sel = 1; w = g_comb[2 * t + 1]; }
        unsigned m = __ballot_sync(0xFFFFFFFFu, sel);
        if (lane == 0) wsum[wrp] = __popc(m);
        __syncthreads();
        int woff = 0, tot = 0;
#pragma unroll
        for (int i = 0; i < 8; i++) {
            int v = wsum[i];
            tot += v;
            if (i < wrp) woff += v;
        }
        if (sel) {
            int pre = __popc(m & ((1u << lane) - 1u));
            int pos = base + woff + pre;
            g_row_token[pos]  = t;
            g_row_weight[pos] = w;
        }
        base += tot;
        __syncthreads();
    }
}

// ---------------- GEMM1 ----------------
#define G1_KC 32

__global__ __launch_bounds__(256) void gemm1_mma(const __half* __restrict__ xh,
                                                 const __half* __restrict__ w1h,
                                                 const __half* __restrict__ w3h) {
    const int e = blockIdx.z;
    const int count = g_counts[e];
    const int m0 = blockIdx.y * 128;
    if (m0 >= count) return;
    const int n0 = blockIdx.x * 128;
    const int off = g_offsets[e];

    extern __shared__ __half dsm[];
    __shared__ int toks[128];

    const int tid = threadIdx.x;
    const int wid = tid >> 5;
    const int lid = tid & 31;
    const int wm = wid >> 2;
    const int wn = wid & 3;
    const int fr = lid >> 2;
    const int fc = lid & 3;
    const int l8 = lid & 7;
    const int s1 = (lid >> 3) & 1;
    const int s2 = (lid >> 4) & 1;

    if (tid < 128) {
        int r = m0 + tid;
        toks[tid] = (r < count) ? g_row_token[off + r] : 0;
    }
    __syncthreads();

    const __half* W1 = w1h + (size_t)e * HID * DFF + n0;
    const __half* W3 = w3h + (size_t)e * HID * DFF + n0;
    const uint32_t sb = s2u(dsm);

    const uint32_t a_lane = (uint32_t)(((l8 + s1 * 8) * AH_STRIDE + s2 * 8) * 2);
    const uint32_t b_lane = (uint32_t)(((s1 * 8 + l8) * BH_STRIDE + s2 * 8) * 2);

    auto fill = [&](int chunk, int stage) {
        uint32_t base = sb + (uint32_t)stage * G1_STG_B;
        int k0 = chunk * 32;
#pragma unroll
        for (int j = 0; j < 2; j++) {
            int i = tid + j * 256;
            int row = i >> 2, q = i & 3;
            cp16(base + (uint32_t)(row * AH_STRIDE + q * 8) * 2,
                 xh + (size_t)toks[row] * HID + k0 + q * 8);
        }
        uint32_t bb = base + A_HALVES * 2;
#pragma unroll
        for (int j = 0; j < 2; j++) {
            int i = tid + j * 256;
            int k = i >> 4, q = i & 15;
            uint32_t o = (uint32_t)(k * BH_STRIDE + q * 8) * 2;
            cp16(bb + o,                W1 + (size_t)(k0 + k) * DFF + q * 8);
            cp16(bb + B_HALVES * 2 + o, W3 + (size_t)(k0 + k) * DFF + q * 8);
        }
        CP_COMMIT();
    };

    float acc1[4][4][4], acc3[4][4][4];
#pragma unroll
    for (int mi = 0; mi < 4; mi++)
#pragma unroll
        for (int ni = 0; ni < 4; ni++)
#pragma unroll
            for (int v = 0; v < 4; v++) { acc1[mi][ni][v] = 0.f; acc3[mi][ni][v] = 0.f; }

    fill(0, 0); fill(1, 1); fill(2, 2);

    for (int c = 0; c < G1_KC; c++) {
        if (c < G1_KC - 2)       CP_WAIT(2);
        else if (c == G1_KC - 2) CP_WAIT(1);
        else                     CP_WAIT(0);
        __syncthreads();
        if (c + 3 < G1_KC) fill(c + 3, (c + 3) & 3);

        uint32_t stA  = sb + (uint32_t)(c & 3) * G1_STG_B;
        uint32_t stB1 = stA + A_HALVES * 2;
        uint32_t stB3 = stB1 + B_HALVES * 2;

#pragma unroll
        for (int ks = 0; ks < 2; ks++) {
            int kk = ks * 16;
            uint32_t afr[4][4];
#pragma unroll
            for (int mi = 0; mi < 4; mi++)
                ldsm4(afr[mi], stA + (uint32_t)((wm * 64 + mi * 16) * AH_STRIDE + kk) * 2 + a_lane);
            uint32_t b1f[2][4], b3f[2][4];
#pragma unroll
            for (int np = 0; np < 2; np++) {
                uint32_t ba = (uint32_t)(kk * BH_STRIDE + wn * 32 + np * 16) * 2 + b_lane;
                ldsm4t(b1f[np], stB1 + ba);
                ldsm4t(b3f[np], stB3 + ba);
            }
#pragma unroll
            for (int mi = 0; mi < 4; mi++)
#pragma unroll
                for (int np = 0; np < 2; np++) {
                    mma16(acc1[mi][np * 2],     afr[mi], &b1f[np][0]);
                    mma16(acc1[mi][np * 2 + 1], afr[mi], &b1f[np][2]);
                    mma16(acc3[mi][np * 2],     afr[mi], &b3f[np][0]);
                    mma16(acc3[mi][np * 2 + 1], afr[mi], &b3f[np][2]);
                }
        }
    }

#pragma unroll
    for (int mi = 0; mi < 4; mi++) {
        int rA = m0 + wm * 64 + mi * 16 + fr;
        int rB = rA + 8;
#pragma unroll
        for (int ni = 0; ni < 4; ni++) {
            int col = n0 + wn * 32 + ni * 8 + fc * 2;
            if (rA < count) {
                float h0 = acc1[mi][ni][0], h1 = acc1[mi][ni][1];
                float ox = (h0 / (1.f + __expf(-h0))) * acc3[mi][ni][0];
                float oy = (h1 / (1.f + __expf(-h1))) * acc3[mi][ni][1];
                *(__half2*)(g_acth + (size_t)(off + rA) * DFF + col) = __floats2half2_rn(ox, oy);
            }
            if (rB < count) {
                float h2 = acc1[mi][ni][2], h3 = acc1[mi][ni][3];
                float ox = (h2 / (1.f + __expf(-h2))) * acc3[mi][ni][2];
                float oy = (h3 / (1.f + __expf(-h3))) * acc3[mi][ni][3];
                *(__half2*)(g_acth + (size_t)(off + rB) * DFF + col) = __floats2half2_rn(ox, oy);
            }
        }
    }
}

// ---------------- GEMM2 ----------------
#define G2_KC 88

__global__ __launch_bounds__(256) void gemm2_mma(const __half* __restrict__ w2h,
                                                 float* __restrict__ out) {
    const int e = blockIdx.z;
    const int count = g_counts[e];
    const int m0 = blockIdx.y * 128;
    if (m0 >= count) return;
    const int n0 = blockIdx.x * 128;
    const int off = g_offsets[e];

    extern __shared__ __half dsm[];
    __shared__ int   toks[128];
    __shared__ float wts[128];

    const int tid = threadIdx.x;
    const int wid = tid >> 5;
    const int lid = tid & 31;
    const int wm = wid >> 2;
    const int wn = wid & 3;
    const int fr = lid >> 2;
    const int fc = lid & 3;
    const int l8 = lid & 7;
    const int s1 = (lid >> 3) & 1;
    const int s2 = (lid >> 4) & 1;

    if (tid < 128) {
        int r = m0 + tid;
        bool ok = r < count;
        toks[tid] = ok ? g_row_token[off + r] : 0;
        wts[tid]  = ok ? g_row_weight[off + r] : 0.f;
    }
    __syncthreads();

    const __half* W2 = w2h + (size_t)e * DFF * HID + n0;
    const uint32_t sb = s2u(dsm);
    const int arow_base = off + m0;

    const uint32_t a_lane = (uint32_t)(((l8 + s1 * 8) * AH_STRIDE + s2 * 8) * 2);
    const uint32_t b_lane = (uint32_t)(((s1 * 8 + l8) * BH_STRIDE + s2 * 8) * 2);

    auto fill = [&](int chunk, int stage) {
        uint32_t base = sb + (uint32_t)stage * G2_STG_B;
        int k0 = chunk * 32;
#pragma unroll
        for (int j = 0; j < 2; j++) {
            int i = tid + j * 256;
            int row = i >> 2, q = i & 3;
            int ridx = arow_base + row;
            if (ridx > TOTR - 1) ridx = TOTR - 1;
            cp16(base + (uint32_t)(row * AH_STRIDE + q * 8) * 2,
                 g_acth + (size_t)ridx * DFF + k0 + q * 8);
        }
        uint32_t bb = base + A_HALVES * 2;
#pragma unroll
        for (int j = 0; j < 2; j++) {
            int i = tid + j * 256;
            int k = i >> 4, q = i & 15;
            cp16(bb + (uint32_t)(k * BH_STRIDE + q * 8) * 2,
                 W2 + (size_t)(k0 + k) * HID + q * 8);
        }
        CP_COMMIT();
    };

    float acc[4][4][4];
#pragma unroll
    for (int mi = 0; mi < 4; mi++)
#pragma unroll
        for (int ni = 0; ni < 4; ni++)
#pragma unroll
            for (int v = 0; v < 4; v++) acc[mi][ni][v] = 0.f;

    fill(0, 0); fill(1, 1); fill(2, 2);

    for (int c = 0; c < G2_KC; c++) {
        if (c < G2_KC - 2)       CP_WAIT(2);
        else if (c == G2_KC - 2) CP_WAIT(1);
        else                     CP_WAIT(0);
        __syncthreads();
        if (c + 3 < G2_KC) fill(c + 3, (c + 3) & 3);

        uint32_t stA = sb + (uint32_t)(c & 3) * G2_STG_B;
        uint32_t stB = stA + A_HALVES * 2;

#pragma unroll
        for (int ks = 0; ks < 2; ks++) {
            int kk = ks * 16;
            uint32_t afr[4][4];
#pragma unroll
            for (int mi = 0; mi < 4; mi++)
                ldsm4(afr[mi], stA + (uint32_t)((wm * 64 + mi * 16) * AH_STRIDE + kk) * 2 + a_lane);
            uint32_t bf[2][4];
#pragma unroll
            for (int np = 0; np < 2; np++)
                ldsm4t(bf[np], stB + (uint32_t)(kk * BH_STRIDE + wn * 32 + np * 16) * 2 + b_lane);
#pragma unroll
            for (int mi = 0; mi < 4; mi++)
#pragma unroll
                for (int np = 0; np < 2; np++) {
                    mma16(acc[mi][np * 2],     afr[mi], &bf[np][0]);
                    mma16(acc[mi][np * 2 + 1], afr[mi], &bf[np][2]);
                }
        }
    }

#pragma unroll
    for (int mi = 0; mi < 4; mi++) {
        int mlA = wm * 64 + mi * 16 + fr;
        int mlB = mlA + 8;
        int rA = m0 + mlA, rB = m0 + mlB;
        int tkA = toks[mlA], tkB = toks[mlB];
        float wA = wts[mlA], wB = wts[mlB];
#pragma unroll
        for (int ni = 0; ni < 4; ni++) {
            int col = n0 + wn * 32 + ni * 8 + fc * 2;
            if (rA < count) {
                float* d = out + (size_t)tkA * HID + col;
                atomicAdd(d,     wA * acc[mi][ni][0]);
                atomicAdd(d + 1, wA * acc[mi][ni][1]);
            }
            if (rB < count) {
                float* d = out + (size_t)tkB * HID + col;
                atomicAdd(d,     wB * acc[mi][ni][2]);
                atomicAdd(d + 1, wB * acc[mi][ni][3]);
            }
        }
    }
}

// ---------------- launch ----------------
extern "C" void kernel_launch(void* const* d_in, const int* in_sizes, int n_in,
                              void* d_out, int out_size) {
    const float* x  = (const float*)d_in[0];
    const float* gw = (const float*)d_in[1];
    const float* w1 = (const float*)d_in[2];
    const float* w3 = (const float*)d_in[3];
    const float* w2 = (const float*)d_in[4];
    float* out = (float*)d_out;

    void *p_xh, *p_w1h, *p_w3h, *p_w2h;
    cudaGetSymbolAddress(&p_xh,  g_xh);
    cudaGetSymbolAddress(&p_w1h, g_w1h);
    cudaGetSymbolAddress(&p_w3h, g_w3h);
    cudaGetSymbolAddress(&p_w2h, g_w2h);

    static cudaStream_t sB = nullptr, sC = nullptr;
    static cudaEvent_t evFork = nullptr, evA = nullptr, evB = nullptr, evC = nullptr;
    static bool inited = false;
    if (!inited) {
        cudaStreamCreateWithFlags(&sB, cudaStreamNonBlocking);
        cudaStreamCreateWithFlags(&sC, cudaStreamNonBlocking);
        cudaEventCreateWithFlags(&evFork, cudaEventDisableTiming);
        cudaEventCreateWithFlags(&evA, cudaEventDisableTiming);
        cudaEventCreateWithFlags(&evB, cudaEventDisableTiming);
        cudaEventCreateWithFlags(&evC, cudaEventDisableTiming);
        cudaFuncSetAttribute(gemm1_mma, cudaFuncAttributeMaxDynamicSharedMemorySize, G1_SMEM + 1024);
        cudaFuncSetAttribute(gemm2_mma, cudaFuncAttributeMaxDynamicSharedMemorySize, G2_SMEM + 1024);
        inited = true;
    }

    const int n4w = NEXP * HID * DFF / 4;

    cudaEventRecord(evFork, 0);
    cudaStreamWaitEvent(sB, evFork, 0);
    cudaStreamWaitEvent(sC, evFork, 0);

    // branch B: routing chain (gating also converts x to fp16)
    zero_scratch_kernel<<<1, 32, 0, sB>>>();
    gating_kernel<<<T_TOK / 8, 256, 0, sB>>>(x, gw);
    routing_aux_kernel<<<NEXP, 256, 0, sB>>>(out + (size_t)T_TOK * HID,
                                             (out_size > T_TOK * HID) ? 1 : 0);
    cudaEventRecord(evB, sB);

    // main: w1+w3 convert (gemm1's prerequisite), 2x float4/thread + streaming
    {
        dim3 g((n4w + 511) / 512, 1, 2);
        cvt_fp16_w<<<g, 256>>>((const float4*)w1, (__half2*)p_w1h,
                               (const float4*)w3, (__half2*)p_w3h, n4w);
    }
    cudaEventRecord(evA, 0);

    // sC: out zero + w2 convert AFTER cvt13 (hides under gemm1's compute)
    cudaStreamWaitEvent(sC, evA, 0);
    cudaMemsetAsync(out, 0, (size_t)T_TOK * HID * sizeof(float), sC);
    cvt_fp16<<<(n4w + 511) / 512, 256, 0, sC>>>((const float4*)w2, (__half2*)p_w2h, n4w);
    cudaEventRecord(evC, sC);

    // main: gemm1 after routing chain (evB) and cvt13 (program order)
    cudaStreamWaitEvent(0, evB, 0);
    dim3 g1(DFF / 128, T_TOK / 128, NEXP);
    gemm1_mma<<<g1, 256, G1_SMEM + 1024>>>((const __half*)p_xh,
                                           (const __half*)p_w1h,
                                           (const __half*)p_w3h);

    // main: gemm2 after w2 convert + out zero
    cudaStreamWaitEvent(0, evC, 0);
    dim3 g2(HID / 128, T_TOK / 128, NEXP);
    gemm2_mma<<<g2, 256, G2_SMEM + 1024>>>((const __half*)p_w2h, out);
}